// round 13
// baseline (speedup 1.0000x reference)
#include <cuda_runtime.h>

// out = g*(x - trend) + (1-g)*trend = g*x + (1-2g)*trend
// trend[0]=x[0]; trend[l] = 0.7*x[l] + 0.3*trend[l-1]   (per (b,c) sequence)
//
// Parallel decomposition: the recurrence forgets its carry at rate 0.3/step.
// SEG=128 segments with HALO=16 warm-up (damping 0.3^16 ~ 4.3e-9, below the
// chain's own fp32 roundoff). SEG=128 is the traffic-optimal point measured
// across R3..R12: ~521MB DRAM (12.5% halo, largely L2-absorbed) vs ~552MB at
// SEG=64.
//
// Model after R3..R12: DRAM-active is ceilinged at ~78-81% once in-flight
// bytes/SM >= ~50KB, regardless of composition. So: minimize traffic
// (SEG=128) and decouple warp count from the segment count by going
// float2-per-thread — 256-thread blocks, 8 warps each, 8192 warps total
// (2x R5) — with an unroll-8 body (8 batched LDG.64/warp ≈ 2KB in flight
// per warp) at ~48 resident warps/SM.

#define ALPHA 0.7f
#define BETA  0.3f

constexpr int Bdim = 32;
constexpr int Ldim = 4096;
constexpr int Cdim = 512;
constexpr int C2   = Cdim / 2;   // 256 float2 lanes per row
constexpr int SEG  = 128;
constexpr int HALO = 16;
constexpr int NSEG = Ldim / SEG; // 32

__global__ __launch_bounds__(C2, 6)
void star_ema_kernel(const float2* __restrict__ x,
                     const float*  __restrict__ gate,
                     float2*       __restrict__ out) {
    const int c2  = threadIdx.x;        // 0..255  (coalesced across warp)
    const int seg = blockIdx.x;         // 0..NSEG-1
    const int b   = blockIdx.y;         // 0..B-1

    float g = gate[0];
    g = fminf(fmaxf(g, 0.0f), 1.0f);
    const float w = 1.0f - 2.0f * g;    // out = g*x + w*trend

    const float2* __restrict__ xb = x   + (size_t)b * Ldim * C2 + c2;
    float2*       __restrict__ ob = out + (size_t)b * Ldim * C2 + c2;

    const int l0 = seg * SEG;
    float2 t;

    if (seg == 0) {
        // seed carry with x[0]: first main-loop step yields t[0]=0.7x0+0.3x0=x0
        t = xb[0];
    } else {
        // halo warm-up (no writes); initial carry error decays by 0.3^HALO
        const int ls = l0 - HALO;
        t = xb[(size_t)ls * C2];
        #pragma unroll 4
        for (int h = ls + 1; h < l0; ++h) {
            float2 v = xb[(size_t)h * C2];
            t.x = fmaf(BETA, t.x, ALPHA * v.x);
            t.y = fmaf(BETA, t.y, ALPHA * v.y);
        }
    }

    const int lend = l0 + SEG;
    #pragma unroll 8
    for (int l = l0; l < lend; ++l) {
        float2 v = xb[(size_t)l * C2];
        t.x = fmaf(BETA, t.x, ALPHA * v.x);
        t.y = fmaf(BETA, t.y, ALPHA * v.y);
        float2 o;
        o.x = fmaf(w, t.x, g * v.x);
        o.y = fmaf(w, t.y, g * v.y);
        ob[(size_t)l * C2] = o;
    }
}

extern "C" void kernel_launch(void* const* d_in, const int* in_sizes, int n_in,
                              void* d_out, int out_size) {
    const float2* x    = (const float2*)d_in[0];
    const float*  gate = (const float*)d_in[1];
    float2*       out  = (float2*)d_out;

    dim3 grid(NSEG, Bdim);
    dim3 block(C2);
    star_ema_kernel<<<grid, block>>>(x, gate, out);
}

// round 14
// speedup vs baseline: 1.0865x; 1.0865x over previous
#include <cuda_runtime.h>

// out = g*(x - trend) + (1-g)*trend = g*x + (1-2g)*trend
// trend[0]=x[0]; trend[l] = 0.7*x[l] + 0.3*trend[l-1]   (per (b,c) sequence)
//
// Parallel decomposition: the recurrence forgets its carry at rate 0.3/step.
// SEG=128 segments, HALO=12 warm-up: carry damping 0.3^12 ~ 5.3e-7, three
// orders below the 1e-3 gate (chain roundoff itself measured ~6e-9).
// SEG=128 is the measured traffic-optimal point (~521MB DRAM vs ~552MB at
// SEG=64); HALO 16->12 shaves the residual halo traffic + 25% of the serial
// warm-up prologue.
//
// Locked-in findings (R3..R13):
//  - float4/LDG.128 mandatory: float2 at 66% occ hit only 65% DRAM (LSU
//    issue-rate floor is per-op; 128-bit requests are the efficient path).
//  - DRAM-active plateaus at ~78-81% for float4 configs with >=~50KB/SM in
//    flight; unroll-4 @ 8 blocks/SM (62 regs) is the best chassis (R5).
//  - __stcs neutral (R12); explicit SW pipelining harmful via regs (R6).

#define ALPHA 0.7f
#define BETA  0.3f

constexpr int Bdim = 32;
constexpr int Ldim = 4096;
constexpr int Cdim = 512;
constexpr int C4   = Cdim / 4;   // 128 float4 lanes per row
constexpr int SEG  = 128;
constexpr int HALO = 12;
constexpr int NSEG = Ldim / SEG; // 32

__global__ __launch_bounds__(C4, 8)
void star_ema_kernel(const float4* __restrict__ x,
                     const float*  __restrict__ gate,
                     float4*       __restrict__ out) {
    const int c4  = threadIdx.x;        // 0..127  (coalesced across warp)
    const int seg = blockIdx.x;         // 0..NSEG-1
    const int b   = blockIdx.y;         // 0..B-1

    float g = gate[0];
    g = fminf(fmaxf(g, 0.0f), 1.0f);
    const float w = 1.0f - 2.0f * g;    // out = g*x + w*trend

    const float4* __restrict__ xb = x   + (size_t)b * Ldim * C4 + c4;
    float4*       __restrict__ ob = out + (size_t)b * Ldim * C4 + c4;

    const int l0 = seg * SEG;
    float4 t;
    int l;

    if (seg == 0) {
        // exact start: trend[0] = x[0]
        float4 v = xb[0];
        t = v;
        float4 o;
        o.x = fmaf(w, t.x, g * v.x);
        o.y = fmaf(w, t.y, g * v.y);
        o.z = fmaf(w, t.z, g * v.z);
        o.w = fmaf(w, t.w, g * v.w);
        ob[0] = o;
        l = 1;
    } else {
        // halo warm-up (no writes); initial carry error decays by 0.3^HALO
        int ls = l0 - HALO;
        t = xb[(size_t)ls * C4];
        #pragma unroll
        for (int h = ls + 1; h < l0; ++h) {
            float4 v = xb[(size_t)h * C4];
            t.x = fmaf(BETA, t.x, ALPHA * v.x);
            t.y = fmaf(BETA, t.y, ALPHA * v.y);
            t.z = fmaf(BETA, t.z, ALPHA * v.z);
            t.w = fmaf(BETA, t.w, ALPHA * v.w);
        }
        l = l0;
    }

    const int lend = l0 + SEG;
    #pragma unroll 4
    for (; l < lend; ++l) {
        float4 v = xb[(size_t)l * C4];
        t.x = fmaf(BETA, t.x, ALPHA * v.x);
        t.y = fmaf(BETA, t.y, ALPHA * v.y);
        t.z = fmaf(BETA, t.z, ALPHA * v.z);
        t.w = fmaf(BETA, t.w, ALPHA * v.w);
        float4 o;
        o.x = fmaf(w, t.x, g * v.x);
        o.y = fmaf(w, t.y, g * v.y);
        o.z = fmaf(w, t.z, g * v.z);
        o.w = fmaf(w, t.w, g * v.w);
        ob[(size_t)l * C4] = o;
    }
}

extern "C" void kernel_launch(void* const* d_in, const int* in_sizes, int n_in,
                              void* d_out, int out_size) {
    const float4* x    = (const float4*)d_in[0];
    const float*  gate = (const float*)d_in[1];
    float4*       out  = (float4*)d_out;

    dim3 grid(NSEG, Bdim);
    dim3 block(C4);
    star_ema_kernel<<<grid, block>>>(x, gate, out);
}

// round 15
// speedup vs baseline: 1.1060x; 1.0180x over previous
#include <cuda_runtime.h>

// out = g*(x - trend) + (1-g)*trend = g*x + (1-2g)*trend
// trend[0]=x[0]; trend[l] = 0.7*x[l] + 0.3*trend[l-1]   (per (b,c) sequence)
//
// Two paths, selected by a grid-uniform runtime branch on w = 1-2*clip(g):
//
//  w == 0 (gate == 0.5 exactly): the trend term is multiplied by zero, so
//    out = g*x elementwise. No recurrence, no halo — a pure streaming
//    scale kernel with no dependent chain (max per-warp MLP).
//
//  w != 0 (general case): R14 chassis — SEG=128 segments, HALO=12 warm-up
//    (carry damping 0.3^12 ~ 5.3e-7, three orders under the 1e-3 gate),
//    float4 lanes, unroll-4, 8 blocks/SM. Measured at the 512MB traffic
//    floor, DRAM ~78%.
//
// Locked-in findings (R3..R14): float4/LDG.128 mandatory (float2 falsified);
// DRAM% plateaus ~78-81% for chained float4 configs; traffic floor reached;
// __stcs neutral; explicit SW pipelining harmful via register pressure.

#define ALPHA 0.7f
#define BETA  0.3f

constexpr int Bdim = 32;
constexpr int Ldim = 4096;
constexpr int Cdim = 512;
constexpr int C4   = Cdim / 4;   // 128 float4 lanes per row
constexpr int SEG  = 128;
constexpr int HALO = 12;
constexpr int NSEG = Ldim / SEG; // 32

__global__ __launch_bounds__(C4, 8)
void star_ema_kernel(const float4* __restrict__ x,
                     const float*  __restrict__ gate,
                     float4*       __restrict__ out) {
    const int c4  = threadIdx.x;        // 0..127  (coalesced across warp)
    const int seg = blockIdx.x;         // 0..NSEG-1
    const int b   = blockIdx.y;         // 0..B-1

    float g = gate[0];
    g = fminf(fmaxf(g, 0.0f), 1.0f);
    const float w = 1.0f - 2.0f * g;    // out = g*x + w*trend

    const float4* __restrict__ xb = x   + (size_t)b * Ldim * C4 + c4;
    float4*       __restrict__ ob = out + (size_t)b * Ldim * C4 + c4;

    const int l0 = seg * SEG;

    if (w == 0.0f) {
        // trend coefficient is exactly zero -> out = g*x. Pure stream,
        // no carry chain: let ptxas batch loads across the full unroll.
        #pragma unroll 8
        for (int l = l0; l < l0 + SEG; ++l) {
            float4 v = xb[(size_t)l * C4];
            float4 o;
            o.x = g * v.x;
            o.y = g * v.y;
            o.z = g * v.z;
            o.w = g * v.w;
            ob[(size_t)l * C4] = o;
        }
        return;
    }

    // ---- general path: segmented EMA with halo warm-up ----
    float4 t;
    int l;

    if (seg == 0) {
        // exact start: trend[0] = x[0]
        float4 v = xb[0];
        t = v;
        float4 o;
        o.x = fmaf(w, t.x, g * v.x);
        o.y = fmaf(w, t.y, g * v.y);
        o.z = fmaf(w, t.z, g * v.z);
        o.w = fmaf(w, t.w, g * v.w);
        ob[0] = o;
        l = 1;
    } else {
        // halo warm-up (no writes); initial carry error decays by 0.3^HALO
        int ls = l0 - HALO;
        t = xb[(size_t)ls * C4];
        #pragma unroll
        for (int h = ls + 1; h < l0; ++h) {
            float4 v = xb[(size_t)h * C4];
            t.x = fmaf(BETA, t.x, ALPHA * v.x);
            t.y = fmaf(BETA, t.y, ALPHA * v.y);
            t.z = fmaf(BETA, t.z, ALPHA * v.z);
            t.w = fmaf(BETA, t.w, ALPHA * v.w);
        }
        l = l0;
    }

    const int lend = l0 + SEG;
    #pragma unroll 4
    for (; l < lend; ++l) {
        float4 v = xb[(size_t)l * C4];
        t.x = fmaf(BETA, t.x, ALPHA * v.x);
        t.y = fmaf(BETA, t.y, ALPHA * v.y);
        t.z = fmaf(BETA, t.z, ALPHA * v.z);
        t.w = fmaf(BETA, t.w, ALPHA * v.w);
        float4 o;
        o.x = fmaf(w, t.x, g * v.x);
        o.y = fmaf(w, t.y, g * v.y);
        o.z = fmaf(w, t.z, g * v.z);
        o.w = fmaf(w, t.w, g * v.w);
        ob[(size_t)l * C4] = o;
    }
}

extern "C" void kernel_launch(void* const* d_in, const int* in_sizes, int n_in,
                              void* d_out, int out_size) {
    const float4* x    = (const float4*)d_in[0];
    const float*  gate = (const float*)d_in[1];
    float4*       out  = (float4*)d_out;

    dim3 grid(NSEG, Bdim);
    dim3 block(C4);
    star_ema_kernel<<<grid, block>>>(x, gate, out);
}